// round 8
// baseline (speedup 1.0000x reference)
#include <cuda_runtime.h>
#include <cstdint>

#define D      1024
#define LSEQ   2048
#define BATCH  2
#define NH     16
#define DH     64
#define MTOT   (BATCH*LSEQ)

// Scratch (allocation-free rule: __device__ globals)
__device__ float g_q [MTOT*D];
__device__ float g_k [MTOT*D];
__device__ float g_v [MTOT*D];
__device__ float g_ao[MTOT*D];

__device__ __forceinline__ uint32_t cvt_tf32(float f) {
    uint32_t o;
    asm("cvt.rna.tf32.f32 %0, %1;" : "=r"(o) : "f"(f));
    return o;
}

__device__ __forceinline__ void mma_tf32(float* c,
                                         uint32_t a0, uint32_t a1, uint32_t a2, uint32_t a3,
                                         uint32_t b0, uint32_t b1) {
    asm volatile(
        "mma.sync.aligned.m16n8k8.row.col.f32.tf32.tf32.f32 "
        "{%0,%1,%2,%3}, {%4,%5,%6,%7}, {%8,%9}, {%0,%1,%2,%3};\n"
        : "+f"(c[0]), "+f"(c[1]), "+f"(c[2]), "+f"(c[3])
        : "r"(a0), "r"(a1), "r"(a2), "r"(a3), "r"(b0), "r"(b1));
}

// ===========================================================================
// TF32 mma.sync GEMM body: C[M,1024] = A[M,1024] * W[1024,1024]^T (+bias)
// CTA tile 128x128, BK=32, 256 threads (8 warps, warp tile 32x64).
// Smem k-permuted rows: p(k) = (k&3)*8 + ((k&4)?4:0) + (k>>3), pitch 36, so a
// single lds.128 at [row][tig*8(+4)] yields one fragment reg for 4 k-steps.
// MMA issue order: n-tile pairs, ks->mt->n2 innermost => dependent MMAs on the
// same accumulator are 4 apart (covers HMMA latency).
// ===========================================================================
#define PITCH 36
#define TSZ   (128 * PITCH)            // floats per buffer
#define GEMM_SMEM (4 * TSZ * 4)        // As[2] + Bs[2] = 73728 bytes

__device__ __forceinline__ void gemm_body(const float* __restrict__ A,
                                          const float* __restrict__ W,
                                          const float* __restrict__ bias,
                                          float* __restrict__ C,
                                          float* sm)
{
    float* As = sm;              // As[buf][128][36]
    float* Bs = sm + 2 * TSZ;    // Bs[buf][128][36]

    const int tid = threadIdx.x;
    const int m0 = blockIdx.y * 128;
    const int n0 = blockIdx.x * 128;

    const int wid    = tid >> 5;
    const int lane   = tid & 31;
    const int warp_m = wid & 3;          // 0..3 -> 32-row slab
    const int warp_n = wid >> 2;         // 0..1 -> 64-col slab
    const int g      = lane >> 2;        // groupID 0..7
    const int tig    = lane & 3;         // thread-in-group 0..3

    // ---- global load mapping: 4 float4 per thread per matrix per chunk ----
    int lbase[4];
    const float* Ap[4];
    const float* Bp[4];
#pragma unroll
    for (int j = 0; j < 4; j++) {
        int idx = tid + j * 256;         // 0..1023
        int row = idx >> 3;              // 0..127
        int c4  = (idx & 7) * 4;         // k offset 0,4,..28
        lbase[j] = row * PITCH + ((c4 & 4) ? 4 : 0) + (c4 >> 3);
        Ap[j] = A + (size_t)(m0 + row) * D + c4;
        Bp[j] = W + (size_t)(n0 + row) * D + c4;
    }

    float acc[2][8][4];
#pragma unroll
    for (int mt = 0; mt < 2; mt++)
#pragma unroll
        for (int nt = 0; nt < 8; nt++)
#pragma unroll
            for (int r = 0; r < 4; r++) acc[mt][nt][r] = 0.f;

    float4 ra[4], rb[4];

    // ---- prologue: chunk 0 -> buf 0; prefetch chunk 1 ----
#pragma unroll
    for (int j = 0; j < 4; j++) { ra[j] = *(const float4*)(Ap[j]); rb[j] = *(const float4*)(Bp[j]); }
#pragma unroll
    for (int j = 0; j < 4; j++) {
        float* a = As + lbase[j];
        a[0]  = __uint_as_float(cvt_tf32(ra[j].x));
        a[8]  = __uint_as_float(cvt_tf32(ra[j].y));
        a[16] = __uint_as_float(cvt_tf32(ra[j].z));
        a[24] = __uint_as_float(cvt_tf32(ra[j].w));
        float* b = Bs + lbase[j];
        b[0]  = __uint_as_float(cvt_tf32(rb[j].x));
        b[8]  = __uint_as_float(cvt_tf32(rb[j].y));
        b[16] = __uint_as_float(cvt_tf32(rb[j].z));
        b[24] = __uint_as_float(cvt_tf32(rb[j].w));
    }
#pragma unroll
    for (int j = 0; j < 4; j++) { ra[j] = *(const float4*)(Ap[j] + 32); rb[j] = *(const float4*)(Bp[j] + 32); }
    __syncthreads();

    for (int i = 0; i < 32; i++) {
        const int buf = i & 1;

        // store prefetched chunk i+1 into the other buffer
        if (i + 1 < 32) {
            float* Asb = As + ((i + 1) & 1) * TSZ;
            float* Bsb = Bs + ((i + 1) & 1) * TSZ;
#pragma unroll
            for (int j = 0; j < 4; j++) {
                float* a = Asb + lbase[j];
                a[0]  = __uint_as_float(cvt_tf32(ra[j].x));
                a[8]  = __uint_as_float(cvt_tf32(ra[j].y));
                a[16] = __uint_as_float(cvt_tf32(ra[j].z));
                a[24] = __uint_as_float(cvt_tf32(ra[j].w));
                float* b = Bsb + lbase[j];
                b[0]  = __uint_as_float(cvt_tf32(rb[j].x));
                b[8]  = __uint_as_float(cvt_tf32(rb[j].y));
                b[16] = __uint_as_float(cvt_tf32(rb[j].z));
                b[24] = __uint_as_float(cvt_tf32(rb[j].w));
            }
        }
        // kick off loads for chunk i+2
        if (i + 2 < 32) {
            const int koff = (i + 2) * 32;
#pragma unroll
            for (int j = 0; j < 4; j++) { ra[j] = *(const float4*)(Ap[j] + koff); rb[j] = *(const float4*)(Bp[j] + koff); }
        }

        // ---- compute chunk i from buf ----
        const float* Asb = As + buf * TSZ;
        const float* Bsb = Bs + buf * TSZ;

        uint32_t af[2][4][4];   // [mt][areg 0..3][kstep]
#pragma unroll
        for (int mt = 0; mt < 2; mt++) {
            int r = warp_m * 32 + mt * 16 + g;
            float4 t0 = *(const float4*)&Asb[r * PITCH + tig * 8];           // a0, ks0..3
            float4 t1 = *(const float4*)&Asb[r * PITCH + tig * 8 + 4];       // a2
            float4 t2 = *(const float4*)&Asb[(r + 8) * PITCH + tig * 8];     // a1
            float4 t3 = *(const float4*)&Asb[(r + 8) * PITCH + tig * 8 + 4]; // a3
            af[mt][0][0] = __float_as_uint(t0.x); af[mt][0][1] = __float_as_uint(t0.y);
            af[mt][0][2] = __float_as_uint(t0.z); af[mt][0][3] = __float_as_uint(t0.w);
            af[mt][1][0] = __float_as_uint(t2.x); af[mt][1][1] = __float_as_uint(t2.y);
            af[mt][1][2] = __float_as_uint(t2.z); af[mt][1][3] = __float_as_uint(t2.w);
            af[mt][2][0] = __float_as_uint(t1.x); af[mt][2][1] = __float_as_uint(t1.y);
            af[mt][2][2] = __float_as_uint(t1.z); af[mt][2][3] = __float_as_uint(t1.w);
            af[mt][3][0] = __float_as_uint(t3.x); af[mt][3][1] = __float_as_uint(t3.y);
            af[mt][3][2] = __float_as_uint(t3.z); af[mt][3][3] = __float_as_uint(t3.w);
        }

        // n-tile pairs; innermost ks->mt->n2 so same-acc MMAs are 4 apart
#pragma unroll
        for (int ntp = 0; ntp < 4; ntp++) {
            const int nt0 = 2 * ntp;
            int na = warp_n * 64 + nt0 * 8 + g;
            int nb = na + 8;
            float4 u0a = *(const float4*)&Bsb[na * PITCH + tig * 8];
            float4 u1a = *(const float4*)&Bsb[na * PITCH + tig * 8 + 4];
            float4 u0b = *(const float4*)&Bsb[nb * PITCH + tig * 8];
            float4 u1b = *(const float4*)&Bsb[nb * PITCH + tig * 8 + 4];
            uint32_t b0[2][4] = {
                { __float_as_uint(u0a.x), __float_as_uint(u0a.y),
                  __float_as_uint(u0a.z), __float_as_uint(u0a.w) },
                { __float_as_uint(u0b.x), __float_as_uint(u0b.y),
                  __float_as_uint(u0b.z), __float_as_uint(u0b.w) } };
            uint32_t b1[2][4] = {
                { __float_as_uint(u1a.x), __float_as_uint(u1a.y),
                  __float_as_uint(u1a.z), __float_as_uint(u1a.w) },
                { __float_as_uint(u1b.x), __float_as_uint(u1b.y),
                  __float_as_uint(u1b.z), __float_as_uint(u1b.w) } };
#pragma unroll
            for (int ks = 0; ks < 4; ks++)
#pragma unroll
                for (int mt = 0; mt < 2; mt++)
#pragma unroll
                    for (int n2 = 0; n2 < 2; n2++)
                        mma_tf32(acc[mt][nt0 + n2],
                                 af[mt][0][ks], af[mt][1][ks], af[mt][2][ks], af[mt][3][ks],
                                 b0[n2][ks], b1[n2][ks]);
        }
        __syncthreads();
    }

    // ---- epilogue ----
#pragma unroll
    for (int mt = 0; mt < 2; mt++) {
        int row = m0 + warp_m * 32 + mt * 16 + g;
#pragma unroll
        for (int nt = 0; nt < 8; nt++) {
            int col = n0 + warp_n * 64 + nt * 8 + 2 * tig;
            float bx = 0.f, by = 0.f;
            if (bias) { bx = bias[col]; by = bias[col + 1]; }
            float2 v0 = make_float2(acc[mt][nt][0] + bx, acc[mt][nt][1] + by);
            float2 v1 = make_float2(acc[mt][nt][2] + bx, acc[mt][nt][3] + by);
            *(float2*)(C + (size_t)row * D + col)       = v0;
            *(float2*)(C + (size_t)(row + 8) * D + col) = v1;
        }
    }
}

// Fused Q/K/V projection: blockIdx.z selects weight & destination.
__global__ void __launch_bounds__(256, 1) gemm_qkv(const float* __restrict__ x,
                                                   const float* __restrict__ Wq,
                                                   const float* __restrict__ Wk,
                                                   const float* __restrict__ Wv,
                                                   float* __restrict__ Cq,
                                                   float* __restrict__ Ck,
                                                   float* __restrict__ Cv)
{
    extern __shared__ float sm[];
    const int z = blockIdx.z;
    const float* W = (z == 0) ? Wq : (z == 1) ? Wk : Wv;
    float*       C = (z == 0) ? Cq : (z == 1) ? Ck : Cv;
    gemm_body(x, W, nullptr, C, sm);
}

// Output projection (+bias)
__global__ void __launch_bounds__(256, 1) gemm_o(const float* __restrict__ A,
                                                 const float* __restrict__ W,
                                                 const float* __restrict__ bias,
                                                 float* __restrict__ C)
{
    extern __shared__ float sm[];
    gemm_body(A, W, bias, C, sm);
}

// ---------------------------------------------------------------------------
// Sliding-window attention (unchanged, 106us)
// ---------------------------------------------------------------------------
#define QP 68
#define ATTN_SMEM ((64*QP + 128*QP + 128*QP + 64*QP) * 4)

__global__ void __launch_bounds__(256) attn_kernel()
{
    extern __shared__ float fsmem[];
    float* Qs = fsmem;
    float* Ks = Qs + 64 * QP;
    float* Vs = Ks + 128 * QP;
    float* Ps = Vs + 128 * QP;

    const int qstart = blockIdx.x * 64;
    const int h      = blockIdx.y;
    const int b      = blockIdx.z;
    const int tid    = threadIdx.x;

#pragma unroll
    for (int t = 0; t < 4; t++) {
        int v  = tid + t * 256;
        int q  = v >> 4;
        int d4 = (v & 15) * 4;
        float4 val = *(const float4*)(g_q + (size_t)(b * LSEQ + qstart + q) * D + h * DH + d4);
        *(float4*)&Qs[q * QP + d4] = val;
    }
#pragma unroll
    for (int t = 0; t < 8; t++) {
        int v  = tid + t * 256;
        int kl = v >> 4;
        int d4 = (v & 15) * 4;
        int kg = qstart - 32 + kl;
        float4 kv = make_float4(0.f, 0.f, 0.f, 0.f);
        float4 vv = make_float4(0.f, 0.f, 0.f, 0.f);
        if (kg >= 0 && kg < LSEQ) {
            size_t off = (size_t)(b * LSEQ + kg) * D + h * DH + d4;
            kv = *(const float4*)(g_k + off);
            vv = *(const float4*)(g_v + off);
        }
        *(float4*)&Ks[kl * QP + d4] = kv;
        *(float4*)&Vs[kl * QP + d4] = vv;
    }
    __syncthreads();

    const int q = tid >> 2;
    const int s = tid & 3;

    float sc[16];
#pragma unroll
    for (int t = 0; t < 16; t++) sc[t] = 0.f;

    for (int dc = 0; dc < DH; dc += 4) {
        float4 qv = *(float4*)&Qs[q * QP + dc];
#pragma unroll
        for (int t = 0; t < 16; t++) {
            int key = q + s + 4 * t;
            float4 kv = *(float4*)&Ks[key * QP + dc];
            sc[t] += qv.x * kv.x + qv.y * kv.y + qv.z * kv.z + qv.w * kv.w;
        }
    }

    float mx = -1e30f;
#pragma unroll
    for (int t = 0; t < 16; t++) {
        sc[t] *= 0.125f;
        mx = fmaxf(mx, sc[t]);
    }
    mx = fmaxf(mx, __shfl_xor_sync(0xffffffffu, mx, 1));
    mx = fmaxf(mx, __shfl_xor_sync(0xffffffffu, mx, 2));
    float sum = 0.f;
#pragma unroll
    for (int t = 0; t < 16; t++) {
        sc[t] = __expf(sc[t] - mx);
        sum += sc[t];
    }
    sum += __shfl_xor_sync(0xffffffffu, sum, 1);
    sum += __shfl_xor_sync(0xffffffffu, sum, 2);
    float inv = 1.f / sum;
#pragma unroll
    for (int t = 0; t < 16; t++)
        Ps[q * QP + s + 4 * t] = sc[t] * inv;
    __syncthreads();

    float4 a0 = make_float4(0.f, 0.f, 0.f, 0.f);
    float4 a1 = a0, a2 = a0, a3 = a0;
#pragma unroll 4
    for (int j = 0; j < 64; j++) {
        float p = Ps[q * QP + j];
        const float* vr = &Vs[(q + j) * QP + s * 16];
        float4 v0 = *(const float4*)(vr + 0);
        float4 v1 = *(const float4*)(vr + 4);
        float4 v2 = *(const float4*)(vr + 8);
        float4 v3 = *(const float4*)(vr + 12);
        a0.x += p * v0.x; a0.y += p * v0.y; a0.z += p * v0.z; a0.w += p * v0.w;
        a1.x += p * v1.x; a1.y += p * v1.y; a1.z += p * v1.z; a1.w += p * v1.w;
        a2.x += p * v2.x; a2.y += p * v2.y; a2.z += p * v2.z; a2.w += p * v2.w;
        a3.x += p * v3.x; a3.y += p * v3.y; a3.z += p * v3.z; a3.w += p * v3.w;
    }
    float* outp = g_ao + (size_t)(b * LSEQ + qstart + q) * D + h * DH + s * 16;
    *(float4*)(outp + 0)  = a0;
    *(float4*)(outp + 4)  = a1;
    *(float4*)(outp + 8)  = a2;
    *(float4*)(outp + 12) = a3;
}

// ---------------------------------------------------------------------------
extern "C" void kernel_launch(void* const* d_in, const int* in_sizes, int n_in,
                              void* d_out, int out_size)
{
    const float* x  = (const float*)d_in[0];
    const float* Wq = (const float*)d_in[1];
    const float* Wk = (const float*)d_in[2];
    const float* Wv = (const float*)d_in[3];
    const float* Wo = (const float*)d_in[4];
    const float* bo = (const float*)d_in[5];
    float* out = (float*)d_out;

    float *qp, *kp, *vp, *aop;
    cudaGetSymbolAddress((void**)&qp,  g_q);
    cudaGetSymbolAddress((void**)&kp,  g_k);
    cudaGetSymbolAddress((void**)&vp,  g_v);
    cudaGetSymbolAddress((void**)&aop, g_ao);

    cudaFuncSetAttribute(gemm_qkv, cudaFuncAttributeMaxDynamicSharedMemorySize, GEMM_SMEM);
    cudaFuncSetAttribute(gemm_o,   cudaFuncAttributeMaxDynamicSharedMemorySize, GEMM_SMEM);
    cudaFuncSetAttribute(attn_kernel, cudaFuncAttributeMaxDynamicSharedMemorySize, ATTN_SMEM);

    dim3 gqkv(D / 128, MTOT / 128, 3);   // (8, 32, 3) = 768 CTAs
    dim3 go  (D / 128, MTOT / 128);      // (8, 32)

    gemm_qkv<<<gqkv, 256, GEMM_SMEM>>>(x, Wq, Wk, Wv, qp, kp, vp);

    attn_kernel<<<dim3(LSEQ / 64, NH, BATCH), 256, ATTN_SMEM>>>();

    gemm_o<<<go, 256, GEMM_SMEM>>>(aop, Wo, bo, out);
}

// round 9
// speedup vs baseline: 1.4089x; 1.4089x over previous
#include <cuda_runtime.h>
#include <cstdint>

#define D      1024
#define LSEQ   2048
#define BATCH  2
#define NH     16
#define DH     64
#define MTOT   (BATCH*LSEQ)

// Scratch (allocation-free rule: __device__ globals)
__device__ float g_q [MTOT*D];
__device__ float g_k [MTOT*D];
__device__ float g_v [MTOT*D];
__device__ float g_ao[MTOT*D];
__device__ float g_xr[MTOT*D];     // tf32-rounded x
__device__ float g_wr[4][D*D];     // tf32-rounded Wq, Wk, Wv, Wo

__device__ __forceinline__ uint32_t smem_u32(const void* p) {
    uint32_t a;
    asm("{ .reg .u64 t; cvta.to.shared.u64 t, %1; cvt.u32.u64 %0, t; }" : "=r"(a) : "l"(p));
    return a;
}
__device__ __forceinline__ uint32_t cvt_tf32(float f) {
    uint32_t o;
    asm("cvt.rna.tf32.f32 %0, %1;" : "=r"(o) : "f"(f));
    return o;
}
__device__ __forceinline__ void cpa16(uint32_t dst, const float* src) {
    asm volatile("cp.async.cg.shared.global [%0], [%1], 16;" :: "r"(dst), "l"(src) : "memory");
}
#define CPA_COMMIT() asm volatile("cp.async.commit_group;" ::: "memory")
#define CPA_WAIT1()  asm volatile("cp.async.wait_group 1;" ::: "memory")
#define CPA_WAIT0()  asm volatile("cp.async.wait_group 0;" ::: "memory")

__device__ __forceinline__ void mma_tf32(float* c,
                                         uint32_t a0, uint32_t a1, uint32_t a2, uint32_t a3,
                                         uint32_t b0, uint32_t b1) {
    asm volatile(
        "mma.sync.aligned.m16n8k8.row.col.f32.tf32.tf32.f32 "
        "{%0,%1,%2,%3}, {%4,%5,%6,%7}, {%8,%9}, {%0,%1,%2,%3};\n"
        : "+f"(c[0]), "+f"(c[1]), "+f"(c[2]), "+f"(c[3])
        : "r"(a0), "r"(a1), "r"(a2), "r"(a3), "r"(b0), "r"(b1));
}

// ===========================================================================
// Prepass: round fp32 -> tf32-rna bit pattern (elementwise, float4).
// blockIdx.y: 0 = x, 1..4 = Wq,Wk,Wv,Wo
// ===========================================================================
__global__ void __launch_bounds__(256) round_kernel(const float* __restrict__ x,
                                                    const float* __restrict__ Wq,
                                                    const float* __restrict__ Wk,
                                                    const float* __restrict__ Wv,
                                                    const float* __restrict__ Wo)
{
    const int z = blockIdx.y;
    const float* s;
    float* d;
    int n4;
    if (z == 0) { s = x; d = g_xr; n4 = MTOT * D / 4; }
    else {
        s = (z == 1) ? Wq : (z == 2) ? Wk : (z == 3) ? Wv : Wo;
        d = g_wr[z - 1];
        n4 = D * D / 4;
    }
    for (int i = blockIdx.x * blockDim.x + threadIdx.x; i < n4;
         i += gridDim.x * blockDim.x) {
        float4 v = ((const float4*)s)[i];
        v.x = __uint_as_float(cvt_tf32(v.x));
        v.y = __uint_as_float(cvt_tf32(v.y));
        v.z = __uint_as_float(cvt_tf32(v.z));
        v.w = __uint_as_float(cvt_tf32(v.w));
        ((float4*)d)[i] = v;
    }
}

// ===========================================================================
// TF32 mma.sync GEMM: C[M,1024] = A[M,1024] * W[1024,1024]^T (+bias)
// Inputs pre-rounded to tf32. CTA tile 128x128, BK=32, 256 threads, 8 warps
// (warp tile 32x64). cp.async 3-stage pipeline, plain pitch-36 smem rows,
// scalar lds fragment gathers (bank = 4*row+col: conflict-free).
// __launch_bounds__(256,2): 2 CTAs/SM.
// ===========================================================================
#define PITCH 36
#define TSZF  (128 * PITCH)           // floats per matrix per stage (4608)
#define STGF  (2 * TSZF)              // floats per stage (A+B)
#define GEMM_SMEM (3 * STGF * 4)      // 110592 bytes

__device__ __forceinline__ void gemm_body(const float* __restrict__ A,
                                          const float* __restrict__ W,
                                          const float* __restrict__ bias,
                                          float* __restrict__ C,
                                          float* sm)
{
    const int tid = threadIdx.x;
    const int m0 = blockIdx.y * 128;
    const int n0 = blockIdx.x * 128;
    const int wid    = tid >> 5;
    const int lane   = tid & 31;
    const int warp_m = wid & 3;
    const int warp_n = wid >> 2;
    const int g      = lane >> 2;
    const int tig    = lane & 3;

    const uint32_t smb = smem_u32(sm);
    const int r0 = tid >> 3;              // 0..31
    const int c4 = (tid & 7) * 4;         // 0,4,..,28
    const float* Ag = A + (size_t)(m0 + r0) * D + c4;
    const float* Bg = W + (size_t)(n0 + r0) * D + c4;
    const uint32_t wA = smb + (uint32_t)(r0 * PITCH + c4) * 4u;
    const uint32_t wB = wA + TSZF * 4u;

    float acc[2][8][4];
#pragma unroll
    for (int mt = 0; mt < 2; mt++)
#pragma unroll
        for (int nt = 0; nt < 8; nt++)
#pragma unroll
            for (int r = 0; r < 4; r++) acc[mt][nt][r] = 0.f;

    // fragment smem base pointers
    const float* a_base = sm + (warp_m * 32 + g) * PITCH + tig;
    const float* b_base = sm + TSZF + (warp_n * 64 + g) * PITCH + tig;

    // ---- prologue: stages 0,1 <- chunks 0,1 ----
#pragma unroll
    for (int st = 0; st < 2; st++) {
        const uint32_t so = st * (STGF * 4u);
        const int k0 = st * 32;
#pragma unroll
        for (int j = 0; j < 4; j++) {
            cpa16(wA + so + j * (32 * PITCH * 4u), Ag + (size_t)j * 32 * D + k0);
            cpa16(wB + so + j * (32 * PITCH * 4u), Bg + (size_t)j * 32 * D + k0);
        }
        CPA_COMMIT();
    }

    for (int i = 0; i < 32; i++) {
        if (i < 31) CPA_WAIT1(); else CPA_WAIT0();
        __syncthreads();

        // issue chunk i+2 into stage (i+2)%3
        if (i + 2 < 32) {
            const int st = (i + 2) % 3;
            const uint32_t so = st * (STGF * 4u);
            const int k0 = (i + 2) * 32;
#pragma unroll
            for (int j = 0; j < 4; j++) {
                cpa16(wA + so + j * (32 * PITCH * 4u), Ag + (size_t)j * 32 * D + k0);
                cpa16(wB + so + j * (32 * PITCH * 4u), Bg + (size_t)j * 32 * D + k0);
            }
            CPA_COMMIT();
        }

        // ---- compute chunk i from stage i%3 ----
        const int stg = i % 3;
        const float* Ab = a_base + stg * STGF;
        const float* Bb = b_base + stg * STGF;

#pragma unroll
        for (int h = 0; h < 2; h++) {
            // A fragments for ks = 2h, 2h+1
            float af0[2][2], af1[2][2], af2[2][2], af3[2][2];
#pragma unroll
            for (int mt = 0; mt < 2; mt++) {
#pragma unroll
                for (int kk = 0; kk < 2; kk++) {
                    const float* p = Ab + mt * (16 * PITCH) + 8 * (2 * h + kk);
                    af0[mt][kk] = p[0];
                    af1[mt][kk] = p[8 * PITCH];
                    af2[mt][kk] = p[4];
                    af3[mt][kk] = p[8 * PITCH + 4];
                }
            }
#pragma unroll
            for (int ntp = 0; ntp < 4; ntp++) {
                const float* nb = Bb + 2 * ntp * (8 * PITCH);
                float b0[2][2], b1[2][2];
#pragma unroll
                for (int n2 = 0; n2 < 2; n2++) {
#pragma unroll
                    for (int kk = 0; kk < 2; kk++) {
                        const float* p = nb + n2 * (8 * PITCH) + 8 * (2 * h + kk);
                        b0[n2][kk] = p[0];
                        b1[n2][kk] = p[4];
                    }
                }
#pragma unroll
                for (int kk = 0; kk < 2; kk++)
#pragma unroll
                    for (int mt = 0; mt < 2; mt++)
#pragma unroll
                        for (int n2 = 0; n2 < 2; n2++)
                            mma_tf32(acc[mt][2 * ntp + n2],
                                     __float_as_uint(af0[mt][kk]),
                                     __float_as_uint(af1[mt][kk]),
                                     __float_as_uint(af2[mt][kk]),
                                     __float_as_uint(af3[mt][kk]),
                                     __float_as_uint(b0[n2][kk]),
                                     __float_as_uint(b1[n2][kk]));
            }
        }
    }

    // ---- epilogue ----
#pragma unroll
    for (int mt = 0; mt < 2; mt++) {
        int row = m0 + warp_m * 32 + mt * 16 + g;
#pragma unroll
        for (int nt = 0; nt < 8; nt++) {
            int col = n0 + warp_n * 64 + nt * 8 + 2 * tig;
            float bx = 0.f, by = 0.f;
            if (bias) { bx = bias[col]; by = bias[col + 1]; }
            float2 v0 = make_float2(acc[mt][nt][0] + bx, acc[mt][nt][1] + by);
            float2 v1 = make_float2(acc[mt][nt][2] + bx, acc[mt][nt][3] + by);
            *(float2*)(C + (size_t)row * D + col)       = v0;
            *(float2*)(C + (size_t)(row + 8) * D + col) = v1;
        }
    }
}

// Fused Q/K/V projection: blockIdx.z selects weight & destination.
__global__ void __launch_bounds__(256, 2) gemm_qkv(const float* __restrict__ x,
                                                   float* __restrict__ Cq,
                                                   float* __restrict__ Ck,
                                                   float* __restrict__ Cv)
{
    extern __shared__ float sm[];
    const int z = blockIdx.z;
    const float* W = g_wr[z];
    float*       C = (z == 0) ? Cq : (z == 1) ? Ck : Cv;
    gemm_body(x, W, nullptr, C, sm);
}

// Output projection (+bias)
__global__ void __launch_bounds__(256, 2) gemm_o(const float* __restrict__ A,
                                                 const float* __restrict__ bias,
                                                 float* __restrict__ C)
{
    extern __shared__ float sm[];
    gemm_body(A, g_wr[3], bias, C, sm);
}

// ---------------------------------------------------------------------------
// Sliding-window attention (R1 structure; epilogue now stores tf32-rounded
// g_ao so gemm_o needs no cvt — numerics identical to producer-side cvt).
// ---------------------------------------------------------------------------
#define QP 68
#define ATTN_SMEM ((64*QP + 128*QP + 128*QP + 64*QP) * 4)

__global__ void __launch_bounds__(256) attn_kernel()
{
    extern __shared__ float fsmem[];
    float* Qs = fsmem;
    float* Ks = Qs + 64 * QP;
    float* Vs = Ks + 128 * QP;
    float* Ps = Vs + 128 * QP;

    const int qstart = blockIdx.x * 64;
    const int h      = blockIdx.y;
    const int b      = blockIdx.z;
    const int tid    = threadIdx.x;

#pragma unroll
    for (int t = 0; t < 4; t++) {
        int v  = tid + t * 256;
        int q  = v >> 4;
        int d4 = (v & 15) * 4;
        float4 val = *(const float4*)(g_q + (size_t)(b * LSEQ + qstart + q) * D + h * DH + d4);
        *(float4*)&Qs[q * QP + d4] = val;
    }
#pragma unroll
    for (int t = 0; t < 8; t++) {
        int v  = tid + t * 256;
        int kl = v >> 4;
        int d4 = (v & 15) * 4;
        int kg = qstart - 32 + kl;
        float4 kv = make_float4(0.f, 0.f, 0.f, 0.f);
        float4 vv = make_float4(0.f, 0.f, 0.f, 0.f);
        if (kg >= 0 && kg < LSEQ) {
            size_t off = (size_t)(b * LSEQ + kg) * D + h * DH + d4;
            kv = *(const float4*)(g_k + off);
            vv = *(const float4*)(g_v + off);
        }
        *(float4*)&Ks[kl * QP + d4] = kv;
        *(float4*)&Vs[kl * QP + d4] = vv;
    }
    __syncthreads();

    const int q = tid >> 2;
    const int s = tid & 3;

    float sc[16];
#pragma unroll
    for (int t = 0; t < 16; t++) sc[t] = 0.f;

    for (int dc = 0; dc < DH; dc += 4) {
        float4 qv = *(float4*)&Qs[q * QP + dc];
#pragma unroll
        for (int t = 0; t < 16; t++) {
            int key = q + s + 4 * t;
            float4 kv = *(float4*)&Ks[key * QP + dc];
            sc[t] += qv.x * kv.x + qv.y * kv.y + qv.z * kv.z + qv.w * kv.w;
        }
    }

    float mx = -1e30f;
#pragma unroll
    for (int t = 0; t < 16; t++) {
        sc[t] *= 0.125f;
        mx = fmaxf(mx, sc[t]);
    }
    mx = fmaxf(mx, __shfl_xor_sync(0xffffffffu, mx, 1));
    mx = fmaxf(mx, __shfl_xor_sync(0xffffffffu, mx, 2));
    float sum = 0.f;
#pragma unroll
    for (int t = 0; t < 16; t++) {
        sc[t] = __expf(sc[t] - mx);
        sum += sc[t];
    }
    sum += __shfl_xor_sync(0xffffffffu, sum, 1);
    sum += __shfl_xor_sync(0xffffffffu, sum, 2);
    float inv = 1.f / sum;
#pragma unroll
    for (int t = 0; t < 16; t++)
        Ps[q * QP + s + 4 * t] = sc[t] * inv;
    __syncthreads();

    float4 a0 = make_float4(0.f, 0.f, 0.f, 0.f);
    float4 a1 = a0, a2 = a0, a3 = a0;
#pragma unroll 4
    for (int j = 0; j < 64; j++) {
        float p = Ps[q * QP + j];
        const float* vr = &Vs[(q + j) * QP + s * 16];
        float4 v0 = *(const float4*)(vr + 0);
        float4 v1 = *(const float4*)(vr + 4);
        float4 v2 = *(const float4*)(vr + 8);
        float4 v3 = *(const float4*)(vr + 12);
        a0.x += p * v0.x; a0.y += p * v0.y; a0.z += p * v0.z; a0.w += p * v0.w;
        a1.x += p * v1.x; a1.y += p * v1.y; a1.z += p * v1.z; a1.w += p * v1.w;
        a2.x += p * v2.x; a2.y += p * v2.y; a2.z += p * v2.z; a2.w += p * v2.w;
        a3.x += p * v3.x; a3.y += p * v3.y; a3.z += p * v3.z; a3.w += p * v3.w;
    }
    // store tf32-rounded (A operand of the O-projection GEMM)
    float* outp = g_ao + (size_t)(b * LSEQ + qstart + q) * D + h * DH + s * 16;
    float va[16] = { a0.x, a0.y, a0.z, a0.w, a1.x, a1.y, a1.z, a1.w,
                     a2.x, a2.y, a2.z, a2.w, a3.x, a3.y, a3.z, a3.w };
#pragma unroll
    for (int j4 = 0; j4 < 4; j4++) {
        float4 o;
        o.x = __uint_as_float(cvt_tf32(va[4 * j4 + 0]));
        o.y = __uint_as_float(cvt_tf32(va[4 * j4 + 1]));
        o.z = __uint_as_float(cvt_tf32(va[4 * j4 + 2]));
        o.w = __uint_as_float(cvt_tf32(va[4 * j4 + 3]));
        *(float4*)(outp + 4 * j4) = o;
    }
}

// ---------------------------------------------------------------------------
extern "C" void kernel_launch(void* const* d_in, const int* in_sizes, int n_in,
                              void* d_out, int out_size)
{
    const float* x  = (const float*)d_in[0];
    const float* Wq = (const float*)d_in[1];
    const float* Wk = (const float*)d_in[2];
    const float* Wv = (const float*)d_in[3];
    const float* Wo = (const float*)d_in[4];
    const float* bo = (const float*)d_in[5];
    float* out = (float*)d_out;

    float *qp, *kp, *vp, *aop, *xrp;
    cudaGetSymbolAddress((void**)&qp,  g_q);
    cudaGetSymbolAddress((void**)&kp,  g_k);
    cudaGetSymbolAddress((void**)&vp,  g_v);
    cudaGetSymbolAddress((void**)&aop, g_ao);
    cudaGetSymbolAddress((void**)&xrp, g_xr);

    cudaFuncSetAttribute(gemm_qkv, cudaFuncAttributeMaxDynamicSharedMemorySize, GEMM_SMEM);
    cudaFuncSetAttribute(gemm_o,   cudaFuncAttributeMaxDynamicSharedMemorySize, GEMM_SMEM);
    cudaFuncSetAttribute(attn_kernel, cudaFuncAttributeMaxDynamicSharedMemorySize, ATTN_SMEM);

    round_kernel<<<dim3(512, 5), 256>>>(x, Wq, Wk, Wv, Wo);

    dim3 gqkv(D / 128, MTOT / 128, 3);   // (8, 32, 3)
    gemm_qkv<<<gqkv, 256, GEMM_SMEM>>>(xrp, qp, kp, vp);

    attn_kernel<<<dim3(LSEQ / 64, NH, BATCH), 256, ATTN_SMEM>>>();

    dim3 go(D / 128, MTOT / 128);        // (8, 32)
    gemm_o<<<go, 256, GEMM_SMEM>>>(aop, bo, out);
}